// round 15
// baseline (speedup 1.0000x reference)
#include <cuda_runtime.h>
#include <cuda_fp16.h>
#include <cstdint>

// Problem shape (fixed by the reference)
#define Bv 4
#define Hv 16
#define BHv 64
#define Sv 2048
#define Dv 64
#define TQ 32
#define PSTRH 2056           // halves per exp row (2048 + 8 pad)
#define QSCALE 0.18033688f   // 0.125 * log2(e): scores live in log2 domain
#define NT 512               // 16 warps

#define SMEM_BYTES (TQ * PSTRH * 2)   // 131584: fp16 exp plane (reused as fp32 O partials)

// ------------- global scratch (device statics; no runtime alloc) -------------
// mask, transposed for broadcast loads: [b][qt(64)][word(64)][qrow(32)]
__device__ uint32_t g_maskT[(size_t)Bv * 64 * 64 * 32];
__device__ __half   g_Qhi[(size_t)BHv * Sv * Dv];
// KF[bh][w(16)][j(16)][c(4)][lane(32)] : uint2 fp16 K fragments, warp-contiguous
__device__ uint2    g_KF[(size_t)BHv * 32768];
// VF[bh][slice(16)][cc(16)][nb(4)][lane(32)] : uint2 fp16 transposed-V fragments
__device__ uint2    g_VF[(size_t)BHv * 32768];

// ------------- helpers -------------
__device__ __forceinline__ float ex2f(float x) {
    float r;
    asm("ex2.approx.f32 %0, %1;" : "=f"(r) : "f"(x));
    return r;
}

__device__ __forceinline__ uint32_t smem_u32(const void* p) {
    uint32_t a;
    asm("{ .reg .u64 t; cvta.to.shared.u64 t, %1; cvt.u32.u64 %0, t; }" : "=r"(a) : "l"(p));
    return a;
}

__device__ __forceinline__ void ldsm4(uint32_t* a, uint32_t addr) {
    asm volatile("ldmatrix.sync.aligned.m8n8.x4.shared.b16 {%0,%1,%2,%3}, [%4];"
                 : "=r"(a[0]), "=r"(a[1]), "=r"(a[2]), "=r"(a[3]) : "r"(addr));
}

__device__ __forceinline__ void mma4(float* c, const uint32_t* a, uint32_t b0, uint32_t b1) {
    asm volatile(
        "mma.sync.aligned.m16n8k16.row.col.f32.f16.f16.f32 "
        "{%0,%1,%2,%3}, {%4,%5,%6,%7}, {%8,%9}, {%0,%1,%2,%3};\n"
        : "+f"(c[0]), "+f"(c[1]), "+f"(c[2]), "+f"(c[3])
        : "r"(a[0]), "r"(a[1]), "r"(a[2]), "r"(a[3]), "r"(b0), "r"(b1));
}

// ------------- merged prep kernel -------------
// block ranges: [0,2048) mask-pack | [2048,18432) Q split | [18432,26624) KF | [26624,28672) VF
__global__ void prep_kernel(const float* __restrict__ Q, const float* __restrict__ K,
                            const float* __restrict__ V, const int* __restrict__ mask)
{
    __shared__ float sV[64 * 65];
    const int bx = blockIdx.x;
    const int tid = threadIdx.x;

    if (bx < 2048) {
        // ---- pack + transpose mask bits: dst [b][qt][word][qrow] ----
        int idx = bx * 256 + tid;             // = ((b*2048 + q)*64 + widx)
        const int4* src = reinterpret_cast<const int4*>(mask + (size_t)idx * 32);
        uint32_t bits = 0;
        #pragma unroll
        for (int j = 0; j < 8; ++j) {
            int4 v = src[j];
            bits |= (v.x != 0 ? 1u : 0u) << (4 * j);
            bits |= (v.y != 0 ? 1u : 0u) << (4 * j + 1);
            bits |= (v.z != 0 ? 1u : 0u) << (4 * j + 2);
            bits |= (v.w != 0 ? 1u : 0u) << (4 * j + 3);
        }
        const int widx = idx & 63;
        const int q    = (idx >> 6) & 2047;
        const int b    = idx >> 17;
        const int qt   = q >> 5;
        const int qrow = q & 31;
        g_maskT[(((size_t)(b * 64 + qt)) * 64 + widx) * 32 + qrow] = bits;
    } else if (bx < 18432) {
        // ---- Q hi split, pre-scaled into log2 domain (0.125 * log2e) ----
        size_t i = (size_t)(bx - 2048) * 256 + tid;
        float2 f = reinterpret_cast<const float2*>(Q)[i];
        __half2 h = __floats2half2_rn(f.x * QSCALE, f.y * QSCALE);
        reinterpret_cast<uint32_t*>(g_Qhi)[i] = *reinterpret_cast<uint32_t*>(&h);
    } else if (bx < 26624) {
        // ---- K fragment pack, warp-contiguous layout ----
        size_t i = (size_t)(bx - 18432) * 256 + tid;   // OLD index [tokg][c][t]
        int t = (int)(i & 3);
        int c = (int)((i >> 2) & 3);
        size_t tokg = i >> 4;
        const float* row = K + tokg * Dv;
        float2 fa = *reinterpret_cast<const float2*>(row + c * 16 + 2 * t);
        float2 fb = *reinterpret_cast<const float2*>(row + c * 16 + 8 + 2 * t);
        __half2 ha = __floats2half2_rn(fa.x, fa.y);
        __half2 hb = __floats2half2_rn(fb.x, fb.y);
        const int tok = (int)(tokg & 2047);
        const size_t bhp = tokg >> 11;
        const int w = tok >> 7, j = (tok >> 3) & 15, g = tok & 7;
        g_KF[bhp * 32768 + ((size_t)((w * 16 + j) * 4 + c)) * 32 + g * 4 + t] =
            make_uint2(*reinterpret_cast<uint32_t*>(&ha),
                       *reinterpret_cast<uint32_t*>(&hb));
    } else {
        // ---- V transpose + fragment pack, warp-contiguous layout ----
        const int idx2 = bx - 26624;
        const int tb = idx2 & 31;
        const int bh = idx2 >> 5;
        const float* src = V + ((size_t)bh * Sv + tb * 64) * Dv;
        #pragma unroll
        for (int k = 0; k < 4; ++k) {
            int idx = k * 256 + tid;
            int r = idx >> 4, c4 = (idx & 15) * 4;
            float4 v = *reinterpret_cast<const float4*>(src + r * Dv + c4);
            sV[r * 65 + c4 + 0] = v.x; sV[r * 65 + c4 + 1] = v.y;
            sV[r * 65 + c4 + 2] = v.z; sV[r * 65 + c4 + 3] = v.w;
        }
        __syncthreads();
        #pragma unroll
        for (int k = 0; k < 4; ++k) {
            int oi = k * 256 + tid;        // [d][cl][t]
            int d  = oi >> 4;
            int cl = (oi >> 2) & 3;
            int t  = oi & 3;
            int tk = cl * 16 + 2 * t;
            __half2 h0 = __floats2half2_rn(sV[(tk)     * 65 + d], sV[(tk + 1) * 65 + d]);
            __half2 h1 = __floats2half2_rn(sV[(tk + 8) * 65 + d], sV[(tk + 9) * 65 + d]);
            const int chunk = tb * 4 + cl;
            const int half = d >> 5, nb = (d >> 3) & 3, g = d & 7;
            const int wl = chunk & 7, cc = chunk >> 3;
            g_VF[(size_t)bh * 32768 +
                 ((size_t)((half * 8 + wl) * 16 + cc)) * 128 + nb * 32 + g * 4 + t] =
                make_uint2(*reinterpret_cast<uint32_t*>(&h0),
                           *reinterpret_cast<uint32_t*>(&h1));
        }
    }
}

// ------------- main fused kernel -------------
__global__ __launch_bounds__(NT, 1)
void sdpa_main(float* __restrict__ out, float* __restrict__ attn)
{
    extern __shared__ __align__(16) char smemraw[];
    uint16_t* sPhi = reinterpret_cast<uint16_t*>(smemraw);   // [32][PSTRH] fp16 exp
    float*    sO   = reinterpret_cast<float*>(smemraw);      // reuse: [8][32][66] fp32
    __shared__ float sSum[TQ * 16];   // per (row, warp) partial sums
    __shared__ float sInv[TQ];
    __shared__ int   sFull[TQ];

    const int tid  = threadIdx.x;
    const int w    = tid >> 5;
    const int lane = tid & 31;
    const int g    = lane >> 2;
    const int tig  = lane & 3;
    const int half = w >> 3;     // 0/1 (PV d-half)
    const int wl   = w & 7;      // 0..7 (PV token slice)

    const int qt  = blockIdx.x;
    const int h   = blockIdx.y;
    const int b   = blockIdx.z;
    const int bh  = b * Hv + h;
    const int q0g = qt * TQ;

    // ---- Q fragments (hi only, pre-scaled) for ALL 32 rows: qhi[mt*4+dc] ----
    uint32_t qhi[8][4];
    {
        const uint16_t* qh = reinterpret_cast<const uint16_t*>(g_Qhi)
                             + ((size_t)bh * Sv + q0g) * Dv;
        #pragma unroll
        for (int mt = 0; mt < 2; ++mt) {
            #pragma unroll
            for (int dc = 0; dc < 4; ++dc) {
                const int d0 = dc * 16 + tig * 2;
                const int r0 = mt * 16 + g;
                qhi[mt * 4 + dc][0] = *reinterpret_cast<const uint32_t*>(qh + (size_t)r0       * Dv + d0);
                qhi[mt * 4 + dc][1] = *reinterpret_cast<const uint32_t*>(qh + (size_t)(r0 + 8) * Dv + d0);
                qhi[mt * 4 + dc][2] = *reinterpret_cast<const uint32_t*>(qh + (size_t)r0       * Dv + d0 + 8);
                qhi[mt * 4 + dc][3] = *reinterpret_cast<const uint32_t*>(qh + (size_t)(r0 + 8) * Dv + d0 + 8);
            }
        }
    }

    // ====== Phase 1: scores (log2) -> direct exp2 + masked zero + sum ======
    // K prefetch distance 2 (ring of 4, constant indices under unroll 4)
    {
        const uint2* kbase = g_KF + (size_t)bh * 32768 + w * 2048 + lane;
        const uint32_t* mbase = g_maskT + (((size_t)(b * 64 + qt)) * 64 + w * 4) * 32 + g;
        float os[4] = {0.f, 0.f, 0.f, 0.f};
        uint32_t mw[4];

        uint2 kbuf[4][4];
        #pragma unroll
        for (int c = 0; c < 4; ++c) kbuf[0][c] = kbase[c * 32];
        #pragma unroll
        for (int c = 0; c < 4; ++c) kbuf[1][c] = kbase[128 + c * 32];

        #pragma unroll 4
        for (int j = 0; j < 16; ++j) {
            uint2* cur = kbuf[j & 3];
            if (j < 14) {
                const uint2* kp = kbase + (size_t)(j + 2) * 128;
                uint2* nxt = kbuf[(j + 2) & 3];
                #pragma unroll
                for (int c = 0; c < 4; ++c) nxt[c] = kp[c * 32];
            }
            if ((j & 3) == 0) {
                #pragma unroll
                for (int r = 0; r < 4; ++r)
                    mw[r] = mbase[(j >> 2) * 32 + r * 8];
            }
            const int shift = (j & 3) * 8 + tig * 2;

            float a0[4] = {0.f, 0.f, 0.f, 0.f};
            float a1[4] = {0.f, 0.f, 0.f, 0.f};
            #pragma unroll
            for (int dc = 0; dc < 4; ++dc) {
                mma4(a0, qhi[dc],     cur[dc].x, cur[dc].y);
                mma4(a1, qhi[4 + dc], cur[dc].x, cur[dc].y);
            }

            const int col = w * 128 + j * 8 + tig * 2;
            float vals[8] = {a0[0], a0[1], a0[2], a0[3], a1[0], a1[1], a1[2], a1[3]};
            #pragma unroll
            for (int r = 0; r < 4; ++r) {
                const uint32_t bits = (mw[r] >> shift) & 3u;
                float e0 = ex2f(vals[r * 2]);
                float e1 = ex2f(vals[r * 2 + 1]);
                e0 = (bits & 1u) ? e0 : 0.f;
                e1 = (bits & 2u) ? e1 : 0.f;
                os[r] += e0 + e1;
                __half2 p = __floats2half2_rn(e0, e1);
                *reinterpret_cast<uint32_t*>(sPhi + (g + r * 8) * PSTRH + col) =
                    *reinterpret_cast<uint32_t*>(&p);
            }
        }
        // quad reduce, publish per-warp sums
        #pragma unroll
        for (int r = 0; r < 4; ++r) {
            #pragma unroll
            for (int o = 1; o <= 2; o <<= 1)
                os[r] += __shfl_xor_sync(0xffffffffu, os[r], o);
            if (tig == 0) sSum[(g + r * 8) * 16 + w] = os[r];
        }
    }
    __syncthreads();

    // ====== Phase 2: merge 16 partials per row ======
    {
        const int row  = w * 2 + (lane >> 4);
        const int subl = lane & 15;
        float s = sSum[row * 16 + subl];
        #pragma unroll
        for (int o = 1; o <= 8; o <<= 1)
            s += __shfl_xor_sync(0xffffffffu, s, o);
        if (subl == 0) {
            const bool full = (s == 0.f);          // fully masked row -> uniform weights
            sInv[row]  = full ? (1.0f / 2048.0f) : (1.0f / s);
            sFull[row] = full ? 1 : 0;
        }
    }
    __syncthreads();

    // ====== Patch fully-masked rows to exp = 1.0 (rare; makes stores branch-free) ======
    {
        #pragma unroll 1
        for (int q = 0; q < TQ; ++q) {
            if (sFull[q]) {
                *reinterpret_cast<uint2*>(sPhi + q * PSTRH + tid * 4) =
                    make_uint2(0x3C003C00u, 0x3C003C00u);
            }
        }
    }
    __syncthreads();

    // ====== Phase 3: PV mainloop, LDSM double-buffered, interleaved attn stores ======
    float acc[4][2][4];
    #pragma unroll
    for (int nb = 0; nb < 4; ++nb)
        #pragma unroll
        for (int rg = 0; rg < 2; ++rg)
            #pragma unroll
            for (int k = 0; k < 4; ++k) acc[nb][rg][k] = 0.f;

    {
        const uint2* vbase = g_VF + (size_t)bh * 32768 + (half * 8 + wl) * 2048 + lane;
        const int rowsel = (lane & 7) + ((lane >> 3) & 1) * 8;
        const int colsel = ((lane >> 4) & 1) * 8;
        const uint32_t sbase = smem_u32(sPhi);
        uint32_t abase[2];
        #pragma unroll
        for (int rg = 0; rg < 2; ++rg)
            abase[rg] = sbase + ((rg * 16 + rowsel) * PSTRH + colsel) * 2;

        // attn store mapping: 256 col-threads x 2 rows, 8 cols (one LDS.128) each
        const int colT   = (tid & 255) * 8;     // column (halves)
        const int rowOff = tid >> 8;            // 0/1
        float* ab = attn + ((size_t)bh * Sv + q0g) * Sv + colT;
        const uint16_t* ph = sPhi + colT;

        uint2 vb[2][4];
        #pragma unroll
        for (int nb = 0; nb < 4; ++nb) vb[0][nb] = vbase[nb * 32];

        uint32_t ahi[2][2][4];   // [buf][rg][4] — LDSM double buffer
        ldsm4(ahi[0][0], abase[0] + wl * 32);
        ldsm4(ahi[0][1], abase[1] + wl * 32);

        #pragma unroll 2
        for (int cc = 0; cc < 16; ++cc) {
            uint2* cur = vb[cc & 1];
            uint32_t (*curA)[4] = ahi[cc & 1];
            if (cc < 15) {
                // V prefetch (distance 1)
                const uint2* vp = vbase + (size_t)(cc + 1) * 128;
                uint2* nxt = vb[(cc + 1) & 1];
                #pragma unroll
                for (int nb = 0; nb < 4; ++nb) nxt[nb] = vp[nb * 32];
                // LDSM prefetch (distance 1)
                const int nchunk = (cc + 1) * 8 + wl;
                ldsm4(ahi[(cc + 1) & 1][0], abase[0] + nchunk * 32);
                ldsm4(ahi[(cc + 1) & 1][1], abase[1] + nchunk * 32);
            }

            // interleaved attn store: row 2cc+rowOff, 8 cols via one LDS.128
            {
                const int q = cc * 2 + rowOff;
                const float inv = sInv[q];
                uint4 hw = *reinterpret_cast<const uint4*>(ph + q * PSTRH);
                float2 p0 = __half22float2(*reinterpret_cast<__half2*>(&hw.x));
                float2 p1 = __half22float2(*reinterpret_cast<__half2*>(&hw.y));
                float2 p2 = __half22float2(*reinterpret_cast<__half2*>(&hw.z));
                float2 p3 = __half22float2(*reinterpret_cast<__half2*>(&hw.w));
                float4 o0, o1;
                o0.x = p0.x * inv; o0.y = p0.y * inv;
                o0.z = p1.x * inv; o0.w = p1.y * inv;
                o1.x = p2.x * inv; o1.y = p2.y * inv;
                o1.z = p3.x * inv; o1.w = p3.y * inv;
                float* dst = ab + (size_t)q * Sv;
                *reinterpret_cast<float4*>(dst)     = o0;
                *reinterpret_cast<float4*>(dst + 4) = o1;
            }

            #pragma unroll
            for (int nb = 0; nb < 4; ++nb)
                #pragma unroll
                for (int rg = 0; rg < 2; ++rg)
                    mma4(acc[nb][rg], curA[rg], cur[nb].x, cur[nb].y);
        }
    }
    __syncthreads();   // all sPhi reads done; reuse plane memory for O partials

    // write per-warp partials: sO[wl][row(32)][d(64), stride 66]
    #pragma unroll
    for (int nb = 0; nb < 4; ++nb) {
        const int d0 = (half * 4 + nb) * 8 + tig * 2;
        #pragma unroll
        for (int rg = 0; rg < 2; ++rg) {
            const int r0 = rg * 16 + g;
            *reinterpret_cast<float2*>(sO + (wl * 32 + r0)     * 66 + d0) =
                make_float2(acc[nb][rg][0], acc[nb][rg][1]);
            *reinterpret_cast<float2*>(sO + (wl * 32 + r0 + 8) * 66 + d0) =
                make_float2(acc[nb][rg][2], acc[nb][rg][3]);
        }
    }
    __syncthreads();

    // reduce 8 partials and write O
    {
        #pragma unroll
        for (int k = 0; k < 2; ++k) {
            const int idx = k * NT + tid;     // 0..1023 float2 outputs
            const int row = idx >> 5;
            const int d2  = (idx & 31) * 2;
            float2 s = make_float2(0.f, 0.f);
            #pragma unroll
            for (int ww = 0; ww < 8; ++ww) {
                float2 p = *reinterpret_cast<float2*>(sO + (ww * 32 + row) * 66 + d2);
                s.x += p.x;
                s.y += p.y;
            }
            const float inv = sInv[row];
            *reinterpret_cast<float2*>(out + ((size_t)bh * Sv + q0g + row) * Dv + d2) =
                make_float2(s.x * inv, s.y * inv);
        }
    }
}

// ------------- launch -------------
extern "C" void kernel_launch(void* const* d_in, const int* in_sizes, int n_in,
                              void* d_out, int out_size)
{
    const float* Q    = (const float*)d_in[0];
    const float* K    = (const float*)d_in[1];
    const float* V    = (const float*)d_in[2];
    const int*   mask = (const int*)d_in[3];
    float* out  = (float*)d_out;
    float* attn = out + (size_t)Bv * Hv * Sv * Dv;   // output first, then attn_weights

    prep_kernel<<<28672, 256>>>(Q, K, V, mask);

    cudaFuncSetAttribute(sdpa_main, cudaFuncAttributeMaxDynamicSharedMemorySize, SMEM_BYTES);
    dim3 grid(Sv / TQ, Hv, Bv);   // (64, 16, 4)
    sdpa_main<<<grid, NT, SMEM_BYTES>>>(out, attn);
}

// round 16
// speedup vs baseline: 1.2440x; 1.2440x over previous
#include <cuda_runtime.h>
#include <cuda_fp16.h>
#include <cstdint>

// Problem shape (fixed by the reference)
#define Bv 4
#define Hv 16
#define BHv 64
#define Sv 2048
#define Dv 64
#define TQ 32
#define PSTRH 2056           // halves per exp row (2048 + 8 pad)
#define QSCALE 0.18033688f   // 0.125 * log2(e): scores live in log2 domain
#define NT 512               // 16 warps

#define SMEM_BYTES (TQ * PSTRH * 2)   // 131584: fp16 exp plane (reused as fp32 O partials)

// ------------- global scratch (device statics; no runtime alloc) -------------
// mask, transposed for broadcast loads: [b][qt(64)][word(64)][qrow(32)]
__device__ uint32_t g_maskT[(size_t)Bv * 64 * 64 * 32];
__device__ __half   g_Qhi[(size_t)BHv * Sv * Dv];
// KF[bh][w(16)][j(16)][c(4)][lane(32)] : uint2 fp16 K fragments, warp-contiguous
__device__ uint2    g_KF[(size_t)BHv * 32768];
// VF[bh][slice(16)][cc(16)][nb(4)][lane(32)] : uint2 fp16 transposed-V fragments
__device__ uint2    g_VF[(size_t)BHv * 32768];

// ------------- helpers -------------
__device__ __forceinline__ float ex2f(float x) {
    float r;
    asm("ex2.approx.f32 %0, %1;" : "=f"(r) : "f"(x));
    return r;
}

__device__ __forceinline__ uint32_t smem_u32(const void* p) {
    uint32_t a;
    asm("{ .reg .u64 t; cvta.to.shared.u64 t, %1; cvt.u32.u64 %0, t; }" : "=r"(a) : "l"(p));
    return a;
}

__device__ __forceinline__ void ldsm4(uint32_t* a, uint32_t addr) {
    asm volatile("ldmatrix.sync.aligned.m8n8.x4.shared.b16 {%0,%1,%2,%3}, [%4];"
                 : "=r"(a[0]), "=r"(a[1]), "=r"(a[2]), "=r"(a[3]) : "r"(addr));
}

__device__ __forceinline__ void mma4(float* c, const uint32_t* a, uint32_t b0, uint32_t b1) {
    asm volatile(
        "mma.sync.aligned.m16n8k16.row.col.f32.f16.f16.f32 "
        "{%0,%1,%2,%3}, {%4,%5,%6,%7}, {%8,%9}, {%0,%1,%2,%3};\n"
        : "+f"(c[0]), "+f"(c[1]), "+f"(c[2]), "+f"(c[3])
        : "r"(a[0]), "r"(a[1]), "r"(a[2]), "r"(a[3]), "r"(b0), "r"(b1));
}

// ------------- merged prep kernel -------------
// block ranges: [0,2048) mask-pack | [2048,18432) Q split | [18432,26624) KF | [26624,28672) VF
__global__ void prep_kernel(const float* __restrict__ Q, const float* __restrict__ K,
                            const float* __restrict__ V, const int* __restrict__ mask)
{
    __shared__ float sV[64 * 65];
    const int bx = blockIdx.x;
    const int tid = threadIdx.x;

    if (bx < 2048) {
        // ---- pack + transpose mask bits via warp ballot (coalesced reads) ----
        const int wid  = tid >> 5;
        const int lane = tid & 31;
        const int wbase = bx * 256 + wid * 32;             // word-index base for this warp
        const int* msrc = mask + (size_t)wbase * 32;
        uint32_t myword = 0;
        #pragma unroll
        for (int k = 0; k < 32; ++k) {
            const int v = msrc[(size_t)k * 32 + lane];     // one coalesced 128B line / warp
            const uint32_t bal = __ballot_sync(0xffffffffu, v != 0);
            if (lane == k) myword = bal;
        }
        const int idx  = wbase + lane;                     // this lane's word index
        const int widx = idx & 63;
        const int q    = (idx >> 6) & 2047;
        const int b    = idx >> 17;
        const int qt   = q >> 5;
        const int qrow = q & 31;
        g_maskT[(((size_t)(b * 64 + qt)) * 64 + widx) * 32 + qrow] = myword;
    } else if (bx < 18432) {
        // ---- Q hi split, pre-scaled into log2 domain (0.125 * log2e) ----
        size_t i = (size_t)(bx - 2048) * 256 + tid;
        float2 f = reinterpret_cast<const float2*>(Q)[i];
        __half2 h = __floats2half2_rn(f.x * QSCALE, f.y * QSCALE);
        reinterpret_cast<uint32_t*>(g_Qhi)[i] = *reinterpret_cast<uint32_t*>(&h);
    } else if (bx < 26624) {
        // ---- K fragment pack, warp-contiguous layout ----
        size_t i = (size_t)(bx - 18432) * 256 + tid;   // OLD index [tokg][c][t]
        int t = (int)(i & 3);
        int c = (int)((i >> 2) & 3);
        size_t tokg = i >> 4;
        const float* row = K + tokg * Dv;
        float2 fa = *reinterpret_cast<const float2*>(row + c * 16 + 2 * t);
        float2 fb = *reinterpret_cast<const float2*>(row + c * 16 + 8 + 2 * t);
        __half2 ha = __floats2half2_rn(fa.x, fa.y);
        __half2 hb = __floats2half2_rn(fb.x, fb.y);
        const int tok = (int)(tokg & 2047);
        const size_t bhp = tokg >> 11;
        const int w = tok >> 7, j = (tok >> 3) & 15, g = tok & 7;
        g_KF[bhp * 32768 + ((size_t)((w * 16 + j) * 4 + c)) * 32 + g * 4 + t] =
            make_uint2(*reinterpret_cast<uint32_t*>(&ha),
                       *reinterpret_cast<uint32_t*>(&hb));
    } else {
        // ---- V transpose + fragment pack, warp-contiguous layout ----
        const int idx2 = bx - 26624;
        const int tb = idx2 & 31;
        const int bh = idx2 >> 5;
        const float* src = V + ((size_t)bh * Sv + tb * 64) * Dv;
        #pragma unroll
        for (int k = 0; k < 4; ++k) {
            int idx = k * 256 + tid;
            int r = idx >> 4, c4 = (idx & 15) * 4;
            float4 v = *reinterpret_cast<const float4*>(src + r * Dv + c4);
            sV[r * 65 + c4 + 0] = v.x; sV[r * 65 + c4 + 1] = v.y;
            sV[r * 65 + c4 + 2] = v.z; sV[r * 65 + c4 + 3] = v.w;
        }
        __syncthreads();
        #pragma unroll
        for (int k = 0; k < 4; ++k) {
            int oi = k * 256 + tid;        // [d][cl][t]
            int d  = oi >> 4;
            int cl = (oi >> 2) & 3;
            int t  = oi & 3;
            int tk = cl * 16 + 2 * t;
            __half2 h0 = __floats2half2_rn(sV[(tk)     * 65 + d], sV[(tk + 1) * 65 + d]);
            __half2 h1 = __floats2half2_rn(sV[(tk + 8) * 65 + d], sV[(tk + 9) * 65 + d]);
            const int chunk = tb * 4 + cl;
            const int half = d >> 5, nb = (d >> 3) & 3, g = d & 7;
            const int wl = chunk & 7, cc = chunk >> 3;
            g_VF[(size_t)bh * 32768 +
                 ((size_t)((half * 8 + wl) * 16 + cc)) * 128 + nb * 32 + g * 4 + t] =
                make_uint2(*reinterpret_cast<uint32_t*>(&h0),
                           *reinterpret_cast<uint32_t*>(&h1));
        }
    }
}

// ------------- main fused kernel -------------
__global__ __launch_bounds__(NT, 1)
void sdpa_main(float* __restrict__ out, float* __restrict__ attn)
{
    extern __shared__ __align__(16) char smemraw[];
    uint16_t* sPhi = reinterpret_cast<uint16_t*>(smemraw);   // [32][PSTRH] fp16 exp
    float*    sO   = reinterpret_cast<float*>(smemraw);      // reuse: [8][32][66] fp32
    __shared__ float sSum[TQ * 16];   // per (row, warp) partial sums
    __shared__ float sInv[TQ];
    __shared__ int   sFull[TQ];
    __shared__ int   sAny;

    const int tid  = threadIdx.x;
    const int w    = tid >> 5;
    const int lane = tid & 31;
    const int g    = lane >> 2;
    const int tig  = lane & 3;
    const int half = w >> 3;     // 0/1 (PV d-half)
    const int wl   = w & 7;      // 0..7 (PV token slice)

    const int qt  = blockIdx.x;
    const int h   = blockIdx.y;
    const int b   = blockIdx.z;
    const int bh  = b * Hv + h;
    const int q0g = qt * TQ;

    if (tid == 0) sAny = 0;

    // ---- Q fragments (hi only, pre-scaled) for ALL 32 rows: qhi[mt*4+dc] ----
    uint32_t qhi[8][4];
    {
        const uint16_t* qh = reinterpret_cast<const uint16_t*>(g_Qhi)
                             + ((size_t)bh * Sv + q0g) * Dv;
        #pragma unroll
        for (int mt = 0; mt < 2; ++mt) {
            #pragma unroll
            for (int dc = 0; dc < 4; ++dc) {
                const int d0 = dc * 16 + tig * 2;
                const int r0 = mt * 16 + g;
                qhi[mt * 4 + dc][0] = *reinterpret_cast<const uint32_t*>(qh + (size_t)r0       * Dv + d0);
                qhi[mt * 4 + dc][1] = *reinterpret_cast<const uint32_t*>(qh + (size_t)(r0 + 8) * Dv + d0);
                qhi[mt * 4 + dc][2] = *reinterpret_cast<const uint32_t*>(qh + (size_t)r0       * Dv + d0 + 8);
                qhi[mt * 4 + dc][3] = *reinterpret_cast<const uint32_t*>(qh + (size_t)(r0 + 8) * Dv + d0 + 8);
            }
        }
    }

    // ====== Phase 1: scores (log2) -> direct exp2 + masked zero + sum ======
    {
        const uint2* kbase = g_KF + (size_t)bh * 32768 + w * 2048 + lane;
        const uint32_t* mbase = g_maskT + (((size_t)(b * 64 + qt)) * 64 + w * 4) * 32 + g;
        float os[4] = {0.f, 0.f, 0.f, 0.f};
        uint32_t mw[4];

        uint2 kbuf[2][4];
        #pragma unroll
        for (int c = 0; c < 4; ++c) kbuf[0][c] = kbase[c * 32];

        #pragma unroll 4
        for (int j = 0; j < 16; ++j) {
            uint2* cur = kbuf[j & 1];
            if (j < 15) {
                const uint2* kp = kbase + (size_t)(j + 1) * 128;
                uint2* nxt = kbuf[(j + 1) & 1];
                #pragma unroll
                for (int c = 0; c < 4; ++c) nxt[c] = kp[c * 32];
            }
            if ((j & 3) == 0) {
                #pragma unroll
                for (int r = 0; r < 4; ++r)
                    mw[r] = mbase[(j >> 2) * 32 + r * 8];
            }
            const int shift = (j & 3) * 8 + tig * 2;

            float a0[4] = {0.f, 0.f, 0.f, 0.f};
            float a1[4] = {0.f, 0.f, 0.f, 0.f};
            #pragma unroll
            for (int dc = 0; dc < 4; ++dc) {
                mma4(a0, qhi[dc],     cur[dc].x, cur[dc].y);
                mma4(a1, qhi[4 + dc], cur[dc].x, cur[dc].y);
            }

            const int col = w * 128 + j * 8 + tig * 2;
            float vals[8] = {a0[0], a0[1], a0[2], a0[3], a1[0], a1[1], a1[2], a1[3]};
            #pragma unroll
            for (int r = 0; r < 4; ++r) {
                const uint32_t bits = (mw[r] >> shift) & 3u;
                float e0 = ex2f(vals[r * 2]);
                float e1 = ex2f(vals[r * 2 + 1]);
                e0 = (bits & 1u) ? e0 : 0.f;
                e1 = (bits & 2u) ? e1 : 0.f;
                os[r] += e0 + e1;
                __half2 p = __floats2half2_rn(e0, e1);
                *reinterpret_cast<uint32_t*>(sPhi + (g + r * 8) * PSTRH + col) =
                    *reinterpret_cast<uint32_t*>(&p);
            }
        }
        // quad reduce, publish per-warp sums
        #pragma unroll
        for (int r = 0; r < 4; ++r) {
            #pragma unroll
            for (int o = 1; o <= 2; o <<= 1)
                os[r] += __shfl_xor_sync(0xffffffffu, os[r], o);
            if (tig == 0) sSum[(g + r * 8) * 16 + w] = os[r];
        }
    }
    __syncthreads();

    // ====== Phase 2: merge 16 partials per row ======
    {
        const int row  = w * 2 + (lane >> 4);
        const int subl = lane & 15;
        float s = sSum[row * 16 + subl];
        #pragma unroll
        for (int o = 1; o <= 8; o <<= 1)
            s += __shfl_xor_sync(0xffffffffu, s, o);
        if (subl == 0) {
            const bool full = (s == 0.f);          // fully masked row -> uniform weights
            sInv[row]  = full ? (1.0f / 2048.0f) : (1.0f / s);
            sFull[row] = full ? 1 : 0;
            if (full) sAny = 1;
        }
    }
    __syncthreads();

    // ====== Patch fully-masked rows to exp = 1.0 (vanishingly rare; guarded) ======
    if (sAny) {
        #pragma unroll 1
        for (int q = 0; q < TQ; ++q) {
            if (sFull[q]) {
                *reinterpret_cast<uint2*>(sPhi + q * PSTRH + tid * 4) =
                    make_uint2(0x3C003C00u, 0x3C003C00u);
            }
        }
        __syncthreads();
    }

    // ====== Phase 3: PV mainloop with interleaved attn-weight stores (all 16 warps) ======
    float acc[4][2][4];
    #pragma unroll
    for (int nb = 0; nb < 4; ++nb)
        #pragma unroll
        for (int rg = 0; rg < 2; ++rg)
            #pragma unroll
            for (int k = 0; k < 4; ++k) acc[nb][rg][k] = 0.f;

    {
        const uint2* vbase = g_VF + (size_t)bh * 32768 + (half * 8 + wl) * 2048 + lane;
        const int rowsel = (lane & 7) + ((lane >> 3) & 1) * 8;
        const int colsel = ((lane >> 4) & 1) * 8;
        const uint32_t sbase = smem_u32(sPhi);
        uint32_t abase[2];
        #pragma unroll
        for (int rg = 0; rg < 2; ++rg)
            abase[rg] = sbase + ((rg * 16 + rowsel) * PSTRH + colsel) * 2;

        float* ab = attn + ((size_t)bh * Sv + q0g) * Sv + tid * 4;
        const uint16_t* ph = sPhi + tid * 4;

        uint2 vb[2][4];
        #pragma unroll
        for (int nb = 0; nb < 4; ++nb) vb[0][nb] = vbase[nb * 32];

        #pragma unroll 2
        for (int cc = 0; cc < 16; ++cc) {
            uint2* cur = vb[cc & 1];
            const int chunk = cc * 8 + wl;         // 16-token chunk index (0..127)
            if (cc < 15) {
                const uint2* vp = vbase + (size_t)(cc + 1) * 128;
                uint2* nxt = vb[(cc + 1) & 1];
                #pragma unroll
                for (int nb = 0; nb < 4; ++nb) nxt[nb] = vp[nb * 32];
            }
            uint32_t ahi[2][4];
            ldsm4(ahi[0], abase[0] + chunk * 32);
            ldsm4(ahi[1], abase[1] + chunk * 32);

            // interleaved attn store: rows 2cc, 2cc+1 (fire-and-forget streaming STGs
            // fill the scoreboard-stall shadows of the LDG/LDSM->MMA chains)
            #pragma unroll
            for (int rr = 0; rr < 2; ++rr) {
                const int q = cc * 2 + rr;
                const float inv = sInv[q];
                uint2 hw = *reinterpret_cast<const uint2*>(ph + q * PSTRH);
                float2 p0 = __half22float2(*reinterpret_cast<__half2*>(&hw.x));
                float2 p1 = __half22float2(*reinterpret_cast<__half2*>(&hw.y));
                float4 o;
                o.x = p0.x * inv; o.y = p0.y * inv;
                o.z = p1.x * inv; o.w = p1.y * inv;
                __stcs(reinterpret_cast<float4*>(ab + (size_t)q * Sv), o);
            }

            #pragma unroll
            for (int nb = 0; nb < 4; ++nb)
                #pragma unroll
                for (int rg = 0; rg < 2; ++rg)
                    mma4(acc[nb][rg], ahi[rg], cur[nb].x, cur[nb].y);
        }
    }
    __syncthreads();   // all sPhi reads done; reuse plane memory for O partials

    // write per-warp partials: sO[wl][row(32)][d(64), stride 66]
    #pragma unroll
    for (int nb = 0; nb < 4; ++nb) {
        const int d0 = (half * 4 + nb) * 8 + tig * 2;
        #pragma unroll
        for (int rg = 0; rg < 2; ++rg) {
            const int r0 = rg * 16 + g;
            *reinterpret_cast<float2*>(sO + (wl * 32 + r0)     * 66 + d0) =
                make_float2(acc[nb][rg][0], acc[nb][rg][1]);
            *reinterpret_cast<float2*>(sO + (wl * 32 + r0 + 8) * 66 + d0) =
                make_float2(acc[nb][rg][2], acc[nb][rg][3]);
        }
    }
    __syncthreads();

    // reduce 8 partials and write O
    {
        #pragma unroll
        for (int k = 0; k < 2; ++k) {
            const int idx = k * NT + tid;     // 0..1023 float2 outputs
            const int row = idx >> 5;
            const int d2  = (idx & 31) * 2;
            float2 s = make_float2(0.f, 0.f);
            #pragma unroll
            for (int ww = 0; ww < 8; ++ww) {
                float2 p = *reinterpret_cast<float2*>(sO + (ww * 32 + row) * 66 + d2);
                s.x += p.x;
                s.y += p.y;
            }
            const float inv = sInv[row];
            __stcs(reinterpret_cast<float2*>(out + ((size_t)bh * Sv + q0g + row) * Dv + d2),
                   make_float2(s.x * inv, s.y * inv));
        }
    }
}

// ------------- launch -------------
extern "C" void kernel_launch(void* const* d_in, const int* in_sizes, int n_in,
                              void* d_out, int out_size)
{
    const float* Q    = (const float*)d_in[0];
    const float* K    = (const float*)d_in[1];
    const float* V    = (const float*)d_in[2];
    const int*   mask = (const int*)d_in[3];
    float* out  = (float*)d_out;
    float* attn = out + (size_t)Bv * Hv * Sv * Dv;   // output first, then attn_weights

    prep_kernel<<<28672, 256>>>(Q, K, V, mask);

    cudaFuncSetAttribute(sdpa_main, cudaFuncAttributeMaxDynamicSharedMemorySize, SMEM_BYTES);
    dim3 grid(Sv / TQ, Hv, Bv);   // (64, 16, 4)
    sdpa_main<<<grid, NT, SMEM_BYTES>>>(out, attn);
}

// round 17
// speedup vs baseline: 1.2631x; 1.0154x over previous
#include <cuda_runtime.h>
#include <cuda_fp16.h>
#include <cstdint>

// Problem shape (fixed by the reference)
#define Bv 4
#define Hv 16
#define BHv 64
#define Sv 2048
#define Dv 64
#define TQ 32
#define PSTRH 2056           // halves per exp row (2048 + 8 pad)
#define QSCALE 0.18033688f   // 0.125 * log2(e): scores live in log2 domain
#define NT 512               // 16 warps

#define SMEM_BYTES (TQ * PSTRH * 2)   // 131584: fp16 exp plane (reused as fp32 O partials)

// ------------- global scratch (device statics; no runtime alloc) -------------
// mask, transposed for broadcast loads: [b][qt(64)][word(64)][qrow(32)]
__device__ uint32_t g_maskT[(size_t)Bv * 64 * 64 * 32];
__device__ __half   g_Qhi[(size_t)BHv * Sv * Dv];
// KF[bh][w(16)][j(16)][c(4)][lane(32)] : uint2 fp16 K fragments, warp-contiguous
__device__ uint2    g_KF[(size_t)BHv * 32768];
// VF[bh][slice(16)][cc(16)][nb(4)][lane(32)] : uint2 fp16 transposed-V fragments
__device__ uint2    g_VF[(size_t)BHv * 32768];

// ------------- helpers -------------
__device__ __forceinline__ float ex2f(float x) {
    float r;
    asm("ex2.approx.f32 %0, %1;" : "=f"(r) : "f"(x));
    return r;
}

__device__ __forceinline__ uint32_t smem_u32(const void* p) {
    uint32_t a;
    asm("{ .reg .u64 t; cvta.to.shared.u64 t, %1; cvt.u32.u64 %0, t; }" : "=r"(a) : "l"(p));
    return a;
}

__device__ __forceinline__ void ldsm4(uint32_t* a, uint32_t addr) {
    asm volatile("ldmatrix.sync.aligned.m8n8.x4.shared.b16 {%0,%1,%2,%3}, [%4];"
                 : "=r"(a[0]), "=r"(a[1]), "=r"(a[2]), "=r"(a[3]) : "r"(addr));
}

__device__ __forceinline__ void mma4(float* c, const uint32_t* a, uint32_t b0, uint32_t b1) {
    asm volatile(
        "mma.sync.aligned.m16n8k16.row.col.f32.f16.f16.f32 "
        "{%0,%1,%2,%3}, {%4,%5,%6,%7}, {%8,%9}, {%0,%1,%2,%3};\n"
        : "+f"(c[0]), "+f"(c[1]), "+f"(c[2]), "+f"(c[3])
        : "r"(a[0]), "r"(a[1]), "r"(a[2]), "r"(a[3]), "r"(b0), "r"(b1));
}

// ------------- merged prep kernel -------------
// block ranges: [0,2048) mask-pack | [2048,18432) Q split | [18432,26624) KF | [26624,28672) VF
__global__ void prep_kernel(const float* __restrict__ Q, const float* __restrict__ K,
                            const float* __restrict__ V, const int* __restrict__ mask)
{
    __shared__ float sV[64 * 65];
    const int bx = blockIdx.x;
    const int tid = threadIdx.x;

    if (bx < 2048) {
        // ---- pack + transpose mask bits via warp ballot (coalesced reads) ----
        const int wid  = tid >> 5;
        const int lane = tid & 31;
        const int wbase = bx * 256 + wid * 32;             // word-index base for this warp
        const int* msrc = mask + (size_t)wbase * 32;
        uint32_t myword = 0;
        #pragma unroll
        for (int k = 0; k < 32; ++k) {
            const int v = msrc[(size_t)k * 32 + lane];     // one coalesced 128B line / warp
            const uint32_t bal = __ballot_sync(0xffffffffu, v != 0);
            if (lane == k) myword = bal;
        }
        const int idx  = wbase + lane;                     // this lane's word index
        const int widx = idx & 63;
        const int q    = (idx >> 6) & 2047;
        const int b    = idx >> 17;
        const int qt   = q >> 5;
        const int qrow = q & 31;
        g_maskT[(((size_t)(b * 64 + qt)) * 64 + widx) * 32 + qrow] = myword;
    } else if (bx < 18432) {
        // ---- Q hi split, pre-scaled into log2 domain (0.125 * log2e) ----
        size_t i = (size_t)(bx - 2048) * 256 + tid;
        float2 f = reinterpret_cast<const float2*>(Q)[i];
        __half2 h = __floats2half2_rn(f.x * QSCALE, f.y * QSCALE);
        reinterpret_cast<uint32_t*>(g_Qhi)[i] = *reinterpret_cast<uint32_t*>(&h);
    } else if (bx < 26624) {
        // ---- K fragment pack, warp-contiguous layout ----
        size_t i = (size_t)(bx - 18432) * 256 + tid;   // OLD index [tokg][c][t]
        int t = (int)(i & 3);
        int c = (int)((i >> 2) & 3);
        size_t tokg = i >> 4;
        const float* row = K + tokg * Dv;
        float2 fa = *reinterpret_cast<const float2*>(row + c * 16 + 2 * t);
        float2 fb = *reinterpret_cast<const float2*>(row + c * 16 + 8 + 2 * t);
        __half2 ha = __floats2half2_rn(fa.x, fa.y);
        __half2 hb = __floats2half2_rn(fb.x, fb.y);
        const int tok = (int)(tokg & 2047);
        const size_t bhp = tokg >> 11;
        const int w = tok >> 7, j = (tok >> 3) & 15, g = tok & 7;
        g_KF[bhp * 32768 + ((size_t)((w * 16 + j) * 4 + c)) * 32 + g * 4 + t] =
            make_uint2(*reinterpret_cast<uint32_t*>(&ha),
                       *reinterpret_cast<uint32_t*>(&hb));
    } else {
        // ---- V transpose + fragment pack, warp-contiguous layout ----
        const int idx2 = bx - 26624;
        const int tb = idx2 & 31;
        const int bh = idx2 >> 5;
        const float* src = V + ((size_t)bh * Sv + tb * 64) * Dv;
        #pragma unroll
        for (int k = 0; k < 4; ++k) {
            int idx = k * 256 + tid;
            int r = idx >> 4, c4 = (idx & 15) * 4;
            float4 v = *reinterpret_cast<const float4*>(src + r * Dv + c4);
            sV[r * 65 + c4 + 0] = v.x; sV[r * 65 + c4 + 1] = v.y;
            sV[r * 65 + c4 + 2] = v.z; sV[r * 65 + c4 + 3] = v.w;
        }
        __syncthreads();
        #pragma unroll
        for (int k = 0; k < 4; ++k) {
            int oi = k * 256 + tid;        // [d][cl][t]
            int d  = oi >> 4;
            int cl = (oi >> 2) & 3;
            int t  = oi & 3;
            int tk = cl * 16 + 2 * t;
            __half2 h0 = __floats2half2_rn(sV[(tk)     * 65 + d], sV[(tk + 1) * 65 + d]);
            __half2 h1 = __floats2half2_rn(sV[(tk + 8) * 65 + d], sV[(tk + 9) * 65 + d]);
            const int chunk = tb * 4 + cl;
            const int half = d >> 5, nb = (d >> 3) & 3, g = d & 7;
            const int wl = chunk & 7, cc = chunk >> 3;
            g_VF[(size_t)bh * 32768 +
                 ((size_t)((half * 8 + wl) * 16 + cc)) * 128 + nb * 32 + g * 4 + t] =
                make_uint2(*reinterpret_cast<uint32_t*>(&h0),
                           *reinterpret_cast<uint32_t*>(&h1));
        }
    }
}

// ------------- main fused kernel -------------
__global__ __launch_bounds__(NT, 1)
void sdpa_main(float* __restrict__ out, float* __restrict__ attn)
{
    extern __shared__ __align__(16) char smemraw[];
    uint16_t* sPhi = reinterpret_cast<uint16_t*>(smemraw);   // [32][PSTRH] fp16 exp
    float*    sO   = reinterpret_cast<float*>(smemraw);      // reuse: [8][32][66] fp32
    __shared__ float sSum[TQ * 16];   // per (row, warp) partial sums
    __shared__ float sInv[TQ];
    __shared__ int   sFull[TQ];
    __shared__ int   sAny;

    const int tid  = threadIdx.x;
    const int w    = tid >> 5;
    const int lane = tid & 31;
    const int g    = lane >> 2;
    const int tig  = lane & 3;
    const int half = w >> 3;     // 0/1 (PV d-half)
    const int wl   = w & 7;      // 0..7 (PV token slice)

    const int qt  = blockIdx.x;
    const int h   = blockIdx.y;
    const int b   = blockIdx.z;
    const int bh  = b * Hv + h;
    const int q0g = qt * TQ;

    if (tid == 0) sAny = 0;

    // ---- Q fragments (hi only, pre-scaled) for ALL 32 rows: qhi[mt*4+dc] ----
    uint32_t qhi[8][4];
    {
        const uint16_t* qh = reinterpret_cast<const uint16_t*>(g_Qhi)
                             + ((size_t)bh * Sv + q0g) * Dv;
        #pragma unroll
        for (int mt = 0; mt < 2; ++mt) {
            #pragma unroll
            for (int dc = 0; dc < 4; ++dc) {
                const int d0 = dc * 16 + tig * 2;
                const int r0 = mt * 16 + g;
                qhi[mt * 4 + dc][0] = *reinterpret_cast<const uint32_t*>(qh + (size_t)r0       * Dv + d0);
                qhi[mt * 4 + dc][1] = *reinterpret_cast<const uint32_t*>(qh + (size_t)(r0 + 8) * Dv + d0);
                qhi[mt * 4 + dc][2] = *reinterpret_cast<const uint32_t*>(qh + (size_t)r0       * Dv + d0 + 8);
                qhi[mt * 4 + dc][3] = *reinterpret_cast<const uint32_t*>(qh + (size_t)(r0 + 8) * Dv + d0 + 8);
            }
        }
    }

    // ====== Phase 1: scores (log2) -> direct exp2 + masked zero + sum ======
    {
        const uint2* kbase = g_KF + (size_t)bh * 32768 + w * 2048 + lane;
        const uint32_t* mbase = g_maskT + (((size_t)(b * 64 + qt)) * 64 + w * 4) * 32 + g;
        float os[4] = {0.f, 0.f, 0.f, 0.f};
        uint32_t mw[4];

        uint2 kbuf[2][4];
        #pragma unroll
        for (int c = 0; c < 4; ++c) kbuf[0][c] = kbase[c * 32];

        #pragma unroll 4
        for (int j = 0; j < 16; ++j) {
            uint2* cur = kbuf[j & 1];
            if (j < 15) {
                const uint2* kp = kbase + (size_t)(j + 1) * 128;
                uint2* nxt = kbuf[(j + 1) & 1];
                #pragma unroll
                for (int c = 0; c < 4; ++c) nxt[c] = kp[c * 32];
            }
            if ((j & 3) == 0) {
                #pragma unroll
                for (int r = 0; r < 4; ++r)
                    mw[r] = mbase[(j >> 2) * 32 + r * 8];
            }
            const int shift = (j & 3) * 8 + tig * 2;

            float a0[4] = {0.f, 0.f, 0.f, 0.f};
            float a1[4] = {0.f, 0.f, 0.f, 0.f};
            #pragma unroll
            for (int dc = 0; dc < 4; ++dc) {
                mma4(a0, qhi[dc],     cur[dc].x, cur[dc].y);
                mma4(a1, qhi[4 + dc], cur[dc].x, cur[dc].y);
            }

            const int col = w * 128 + j * 8 + tig * 2;
            float vals[8] = {a0[0], a0[1], a0[2], a0[3], a1[0], a1[1], a1[2], a1[3]};
            #pragma unroll
            for (int r = 0; r < 4; ++r) {
                const uint32_t bits = (mw[r] >> shift) & 3u;
                float e0 = ex2f(vals[r * 2]);
                float e1 = ex2f(vals[r * 2 + 1]);
                e0 = (bits & 1u) ? e0 : 0.f;
                e1 = (bits & 2u) ? e1 : 0.f;
                os[r] += e0 + e1;
                __half2 p = __floats2half2_rn(e0, e1);
                *reinterpret_cast<uint32_t*>(sPhi + (g + r * 8) * PSTRH + col) =
                    *reinterpret_cast<uint32_t*>(&p);
            }
        }
        // quad reduce, publish per-warp sums
        #pragma unroll
        for (int r = 0; r < 4; ++r) {
            #pragma unroll
            for (int o = 1; o <= 2; o <<= 1)
                os[r] += __shfl_xor_sync(0xffffffffu, os[r], o);
            if (tig == 0) sSum[(g + r * 8) * 16 + w] = os[r];
        }
    }
    __syncthreads();

    // ====== Phase 2: merge 16 partials per row ======
    {
        const int row  = w * 2 + (lane >> 4);
        const int subl = lane & 15;
        float s = sSum[row * 16 + subl];
        #pragma unroll
        for (int o = 1; o <= 8; o <<= 1)
            s += __shfl_xor_sync(0xffffffffu, s, o);
        if (subl == 0) {
            const bool full = (s == 0.f);          // fully masked row -> uniform weights
            sInv[row]  = full ? (1.0f / 2048.0f) : (1.0f / s);
            sFull[row] = full ? 1 : 0;
            if (full) sAny = 1;
        }
    }
    __syncthreads();

    // ====== Patch fully-masked rows to exp = 1.0 (vanishingly rare; guarded) ======
    if (sAny) {
        #pragma unroll 1
        for (int q = 0; q < TQ; ++q) {
            if (sFull[q]) {
                *reinterpret_cast<uint2*>(sPhi + q * PSTRH + tid * 4) =
                    make_uint2(0x3C003C00u, 0x3C003C00u);
            }
        }
        __syncthreads();
    }

    // ====== Phase 3: PV mainloop, LDSM double-buffered, interleaved attn stores ======
    float acc[4][2][4];
    #pragma unroll
    for (int nb = 0; nb < 4; ++nb)
        #pragma unroll
        for (int rg = 0; rg < 2; ++rg)
            #pragma unroll
            for (int k = 0; k < 4; ++k) acc[nb][rg][k] = 0.f;

    {
        const uint2* vbase = g_VF + (size_t)bh * 32768 + (half * 8 + wl) * 2048 + lane;
        const int rowsel = (lane & 7) + ((lane >> 3) & 1) * 8;
        const int colsel = ((lane >> 4) & 1) * 8;
        const uint32_t sbase = smem_u32(sPhi);
        uint32_t abase[2];
        #pragma unroll
        for (int rg = 0; rg < 2; ++rg)
            abase[rg] = sbase + ((rg * 16 + rowsel) * PSTRH + colsel) * 2;

        float* ab = attn + ((size_t)bh * Sv + q0g) * Sv + tid * 4;
        const uint16_t* ph = sPhi + tid * 4;

        uint2 vb[2][4];
        #pragma unroll
        for (int nb = 0; nb < 4; ++nb) vb[0][nb] = vbase[nb * 32];

        uint32_t ahi[2][2][4];   // [buf][rg][4] — LDSM double buffer
        ldsm4(ahi[0][0], abase[0] + wl * 32);
        ldsm4(ahi[0][1], abase[1] + wl * 32);

        #pragma unroll 2
        for (int cc = 0; cc < 16; ++cc) {
            uint2* cur = vb[cc & 1];
            uint32_t (*curA)[4] = ahi[cc & 1];
            if (cc < 15) {
                // V prefetch (distance 1)
                const uint2* vp = vbase + (size_t)(cc + 1) * 128;
                uint2* nxt = vb[(cc + 1) & 1];
                #pragma unroll
                for (int nb = 0; nb < 4; ++nb) nxt[nb] = vp[nb * 32];
                // LDSM prefetch (distance 1)
                const int nchunk = (cc + 1) * 8 + wl;
                ldsm4(ahi[(cc + 1) & 1][0], abase[0] + nchunk * 32);
                ldsm4(ahi[(cc + 1) & 1][1], abase[1] + nchunk * 32);
            }

            // interleaved attn store: rows 2cc, 2cc+1 (fire-and-forget streaming STGs
            // fill the scoreboard-stall shadows of the LDG/LDSM->MMA chains)
            #pragma unroll
            for (int rr = 0; rr < 2; ++rr) {
                const int q = cc * 2 + rr;
                const float inv = sInv[q];
                uint2 hw = *reinterpret_cast<const uint2*>(ph + q * PSTRH);
                float2 p0 = __half22float2(*reinterpret_cast<__half2*>(&hw.x));
                float2 p1 = __half22float2(*reinterpret_cast<__half2*>(&hw.y));
                float4 o;
                o.x = p0.x * inv; o.y = p0.y * inv;
                o.z = p1.x * inv; o.w = p1.y * inv;
                __stcs(reinterpret_cast<float4*>(ab + (size_t)q * Sv), o);
            }

            #pragma unroll
            for (int nb = 0; nb < 4; ++nb)
                #pragma unroll
                for (int rg = 0; rg < 2; ++rg)
                    mma4(acc[nb][rg], curA[rg], cur[nb].x, cur[nb].y);
        }
    }
    __syncthreads();   // all sPhi reads done; reuse plane memory for O partials

    // write per-warp partials: sO[wl][row(32)][d(64), stride 66]
    #pragma unroll
    for (int nb = 0; nb < 4; ++nb) {
        const int d0 = (half * 4 + nb) * 8 + tig * 2;
        #pragma unroll
        for (int rg = 0; rg < 2; ++rg) {
            const int r0 = rg * 16 + g;
            *reinterpret_cast<float2*>(sO + (wl * 32 + r0)     * 66 + d0) =
                make_float2(acc[nb][rg][0], acc[nb][rg][1]);
            *reinterpret_cast<float2*>(sO + (wl * 32 + r0 + 8) * 66 + d0) =
                make_float2(acc[nb][rg][2], acc[nb][rg][3]);
        }
    }
    __syncthreads();

    // reduce 8 partials and write O
    {
        #pragma unroll
        for (int k = 0; k < 2; ++k) {
            const int idx = k * NT + tid;     // 0..1023 float2 outputs
            const int row = idx >> 5;
            const int d2  = (idx & 31) * 2;
            float2 s = make_float2(0.f, 0.f);
            #pragma unroll
            for (int ww = 0; ww < 8; ++ww) {
                float2 p = *reinterpret_cast<float2*>(sO + (ww * 32 + row) * 66 + d2);
                s.x += p.x;
                s.y += p.y;
            }
            const float inv = sInv[row];
            __stcs(reinterpret_cast<float2*>(out + ((size_t)bh * Sv + q0g + row) * Dv + d2),
                   make_float2(s.x * inv, s.y * inv));
        }
    }
}

// ------------- launch -------------
extern "C" void kernel_launch(void* const* d_in, const int* in_sizes, int n_in,
                              void* d_out, int out_size)
{
    const float* Q    = (const float*)d_in[0];
    const float* K    = (const float*)d_in[1];
    const float* V    = (const float*)d_in[2];
    const int*   mask = (const int*)d_in[3];
    float* out  = (float*)d_out;
    float* attn = out + (size_t)Bv * Hv * Sv * Dv;   // output first, then attn_weights

    prep_kernel<<<28672, 256>>>(Q, K, V, mask);

    cudaFuncSetAttribute(sdpa_main, cudaFuncAttributeMaxDynamicSharedMemorySize, SMEM_BYTES);
    dim3 grid(Sv / TQ, Hv, Bv);   // (64, 16, 4)
    sdpa_main<<<grid, NT, SMEM_BYTES>>>(out, attn);
}